// round 1
// baseline (speedup 1.0000x reference)
#include <cuda_runtime.h>

// Problem constants
#define NS 16
#define NZ 1000
#define NX 1000

#define DT_F    0.001f
#define HDT_F   0.0005f   // dt/2
#define INV_H_F 0.1f      // 1/h

// Tile config: block owns TZ x TX of P; computes (TZ+1) x (TX+1) halo tile in smem
#define TZ  8
#define TX  32
#define TXP (TX + 1)      // 33 (odd width -> conflict-free column-neighbor reads)

__global__ __launch_bounds__(TZ * TX)
void pml_step_kernel(
    const float* __restrict__ Px,   const float* __restrict__ Pz,
    const float* __restrict__ Ax,   const float* __restrict__ Az,
    const float* __restrict__ src,
    const float* __restrict__ m2dt,
    const float* __restrict__ sigx, const float* __restrict__ sxh,
    const float* __restrict__ sigz, const float* __restrict__ szh,
    float* __restrict__ oPx, float* __restrict__ oPz,
    float* __restrict__ oAx, float* __restrict__ oAz,
    float* __restrict__ oP)
{
    __shared__ float sP[TZ + 1][TXP];

    const int s  = blockIdx.z;
    const int z0 = blockIdx.y * TZ;
    const int x0 = blockIdx.x * TX;
    const int tx = threadIdx.x;
    const int ty = threadIdx.y;
    const int tid = ty * TX + tx;

    const int sOffP  = s * (NZ * NX);
    const int sOffAx = s * ((NZ - 2) * (NX - 1));
    const int sOffAz = s * ((NZ - 1) * (NX - 2));

    // ---- Phase 1: compute P over the (TZ+1) x (TX+1) halo tile ----
    #pragma unroll
    for (int idx = tid; idx < (TZ + 1) * TXP; idx += TZ * TX) {
        const int dz = idx / TXP;
        const int dx = idx - dz * TXP;
        const int z = z0 + dz;
        const int x = x0 + dx;
        if (z < NZ && x < NX) {
            float ax_x = 0.0f, az_z = 0.0f;
            if (z >= 1 && z <= NZ - 2 && x >= 1 && x <= NX - 2) {
                // Ax: (NZ-2, NX-1), row z-1, cols x-1..x
                const float* axr = Ax + sOffAx + (z - 1) * (NX - 1);
                ax_x = (axr[x] - axr[x - 1]) * INV_H_F;
                // Az: (NZ-1, NX-2), rows z-1..z, col x-1
                const float* azc = Az + sOffAz + (x - 1);
                az_z = (azc[z * (NX - 2)] - azc[(z - 1) * (NX - 2)]) * INV_H_F;
            }
            const int g2 = z * NX + x;       // 2D coeff index
            const int g3 = sOffP + g2;       // 3D field index
            const float m  = m2dt[g2];
            const float sx = sigx[g2] * HDT_F;
            const float sz = sigz[g2] * HDT_F;
            const float pxn = __fdividef(fmaf(m, ax_x, (1.0f - sx) * Px[g3]), 1.0f + sx);
            const float pzn = __fdividef(fmaf(m, az_z, (1.0f - sz) * Pz[g3]), 1.0f + sz);
            const float p = pxn + pzn + src[g3] * DT_F;
            sP[dz][dx] = p;
            if (dz < TZ && dx < TX) {        // owned region only (halo owned by neighbors)
                oPx[g3] = pxn;
                oPz[g3] = pzn;
                oP[g3]  = p;
            }
        }
    }
    __syncthreads();

    // ---- Phase 2a: Ax_n at (i, j), i = z0-1+ty, j = x0+tx ----
    {
        const int i = z0 - 1 + ty;
        const int j = x0 + tx;
        if (i >= 0 && i < NZ - 2 && j < NX - 1) {
            // P_x(i,j) = (P[i+1][j+1] - P[i+1][j]) / h ; i+1 = z0+ty -> smem row ty
            const float px = (sP[ty][tx + 1] - sP[ty][tx]) * INV_H_F;
            const float sv = sxh[i * (NX - 1) + j] * HDT_F;
            const int g = sOffAx + i * (NX - 1) + j;
            oAx[g] = __fdividef(fmaf(DT_F, px, (1.0f - sv) * Ax[g]), 1.0f + sv);
        }
    }

    // ---- Phase 2b: Az_n at (i, j), i = z0+ty, j = x0-1+tx ----
    {
        const int i = z0 + ty;
        const int j = x0 - 1 + tx;
        if (j >= 0 && i < NZ - 1 && j < NX - 2) {
            // P_z(i,j) = (P[i+1][j+1] - P[i][j+1]) / h ; j+1 = x0+tx -> smem col tx
            const float pz = (sP[ty + 1][tx] - sP[ty][tx]) * INV_H_F;
            const float sv = szh[i * (NX - 2) + j] * HDT_F;
            const int g = sOffAz + i * (NX - 2) + j;
            oAz[g] = __fdividef(fmaf(DT_F, pz, (1.0f - sv) * Az[g]), 1.0f + sv);
        }
    }
}

extern "C" void kernel_launch(void* const* d_in, const int* in_sizes, int n_in,
                              void* d_out, int out_size)
{
    const float* Px   = (const float*)d_in[0];
    const float* Pz   = (const float*)d_in[1];
    const float* Ax   = (const float*)d_in[2];
    const float* Az   = (const float*)d_in[3];
    const float* src  = (const float*)d_in[4];
    const float* m2dt = (const float*)d_in[5];
    const float* sigx = (const float*)d_in[6];
    const float* sxh  = (const float*)d_in[7];
    const float* sigz = (const float*)d_in[8];
    const float* szh  = (const float*)d_in[9];

    float* out = (float*)d_out;
    const long long NP  = (long long)NS * NZ * NX;                 // 16,000,000
    const long long NAX = (long long)NS * (NZ - 2) * (NX - 1);     // 15,952,032
    const long long NAZ = (long long)NS * (NZ - 1) * (NX - 2);     // 15,952,032

    float* oPx = out;
    float* oPz = oPx + NP;
    float* oAx = oPz + NP;
    float* oAz = oAx + NAX;
    float* oP  = oAz + NAZ;

    dim3 block(TX, TZ, 1);
    dim3 grid((NX + TX - 1) / TX, (NZ + TZ - 1) / TZ, NS);

    pml_step_kernel<<<grid, block>>>(Px, Pz, Ax, Az, src,
                                     m2dt, sigx, sxh, sigz, szh,
                                     oPx, oPz, oAx, oAz, oP);
}

// round 2
// speedup vs baseline: 1.3759x; 1.3759x over previous
#include <cuda_runtime.h>

#define NS 16
#define NZ 1000
#define NX 1000

#define DT_F    0.001f
#define HDT_F   0.0005f   // dt/2
#define INV_H_F 0.1f      // 1/h

#define TZ  8
#define TX  128           // tile width (elements); block = 32x8, 4 elems/thread
#define SMW 132           // smem row stride (129 cols used, padded; 132*4B = 33*16B aligned)

// Scalar P computation (halo points only)
__device__ __forceinline__ float compute_p_point(
    const float* __restrict__ Px, const float* __restrict__ Pz,
    const float* __restrict__ Ax, const float* __restrict__ Az,
    const float* __restrict__ src, const float* __restrict__ m2dt,
    const float* __restrict__ sigx, const float* __restrict__ sigz,
    int sOffP, int sOffAx, int sOffAz, int z, int x)
{
    float ax_x = 0.f, az_z = 0.f;
    if (z >= 1 && z <= NZ - 2 && x >= 1 && x <= NX - 2) {
        const float* axr = Ax + sOffAx + (z - 1) * (NX - 1);
        ax_x = (__ldcs(axr + x) - __ldcs(axr + x - 1)) * INV_H_F;
        const float* azp = Az + sOffAz + (x - 1);
        az_z = (__ldcs(azp + z * (NX - 2)) - __ldcs(azp + (z - 1) * (NX - 2))) * INV_H_F;
    }
    const int g2 = z * NX + x;
    const int g3 = sOffP + g2;
    const float sx = sigx[g2] * HDT_F;
    const float sz = sigz[g2] * HDT_F;
    const float m  = m2dt[g2];
    const float pxn = __fdividef(fmaf(m, ax_x, (1.f - sx) * __ldcs(Px + g3)), 1.f + sx);
    const float pzn = __fdividef(fmaf(m, az_z, (1.f - sz) * __ldcs(Pz + g3)), 1.f + sz);
    return pxn + pzn + __ldcs(src + g3) * DT_F;
}

__global__ __launch_bounds__(256)
void pml_step_kernel(
    const float* __restrict__ Px,   const float* __restrict__ Pz,
    const float* __restrict__ Ax,   const float* __restrict__ Az,
    const float* __restrict__ src,
    const float* __restrict__ m2dt,
    const float* __restrict__ sigx, const float* __restrict__ sxh,
    const float* __restrict__ sigz, const float* __restrict__ szh,
    float* __restrict__ oPx, float* __restrict__ oPz,
    float* __restrict__ oAx, float* __restrict__ oAz,
    float* __restrict__ oP)
{
    __shared__ float sP[TZ + 1][SMW];

    const int s  = blockIdx.z;
    const int z0 = blockIdx.y * TZ;
    const int x0 = blockIdx.x * TX;
    const int tx = threadIdx.x;                 // 0..31
    const int ty = threadIdx.y;                 // 0..7
    const int tid = ty * 32 + tx;

    const int sOffP  = s * (NZ * NX);
    const int sOffAx = s * ((NZ - 2) * (NX - 1));
    const int sOffAz = s * ((NZ - 1) * (NX - 2));

    // Registers carried from phase 1 to phase 2:
    //   axk[c+1] = old Ax at (z-1, x+c)  == Ax operand for phase 2a
    //   azk[c]   = old Az at (z,   x-1+c) == Az operand for phase 2b
    float axk[5] = {0.f, 0.f, 0.f, 0.f, 0.f};
    float azk[4] = {0.f, 0.f, 0.f, 0.f};

    const int z = z0 + ty;
    const int x = x0 + 4 * tx;

    // ---- Phase 1: main 8x128 tile, 4 elements/thread (vectorized) ----
    if (x < NX) {   // NX%4==0 and x%4==0 -> vectors are all-in or all-out
        const int g2 = z * NX + x;
        const int g3 = sOffP + g2;
        const float4 pxv = __ldcs((const float4*)(Px + g3));
        const float4 pzv = __ldcs((const float4*)(Pz + g3));
        const float4 srv = __ldcs((const float4*)(src + g3));
        const float4 mv  = *(const float4*)(m2dt + g2);
        const float4 sxv = *(const float4*)(sigx + g2);
        const float4 szv = *(const float4*)(sigz + g2);

        float axx[4] = {0.f, 0.f, 0.f, 0.f};
        float azz[4] = {0.f, 0.f, 0.f, 0.f};

        const bool zin = (z >= 1) && (z <= NZ - 2);
        if (zin) {
            const float* axr  = Ax + sOffAx + (z - 1) * (NX - 1);
            const float* az0r = Az + sOffAz + (z - 1) * (NX - 2);
            const float* az1r = az0r + (NX - 2);
            if (x >= 1 && x + 3 <= NX - 2) {
                // fully interior vector (the overwhelmingly common case)
                const float a0 = __ldcs(axr + x - 1);
                axk[1] = __ldcs(axr + x);
                axk[2] = __ldcs(axr + x + 1);
                axk[3] = __ldcs(axr + x + 2);
                axk[4] = __ldcs(axr + x + 3);
                axx[0] = (axk[1] - a0)     * INV_H_F;
                axx[1] = (axk[2] - axk[1]) * INV_H_F;
                axx[2] = (axk[3] - axk[2]) * INV_H_F;
                axx[3] = (axk[4] - axk[3]) * INV_H_F;
                float azlo[4];
                #pragma unroll
                for (int c = 0; c < 4; c++) {
                    azlo[c] = __ldcs(az0r + x - 1 + c);
                    azk[c]  = __ldcs(az1r + x - 1 + c);
                    azz[c]  = (azk[c] - azlo[c]) * INV_H_F;
                }
            } else {
                // boundary vector: per-component guarded loads
                float azlo[4] = {0.f, 0.f, 0.f, 0.f};
                #pragma unroll
                for (int c = 0; c < 5; c++) {
                    const int col = x - 1 + c;
                    if (col >= 0 && col <= NX - 2) axk[c] = __ldcs(axr + col);
                }
                #pragma unroll
                for (int c = 0; c < 4; c++) {
                    const int col = x - 1 + c;
                    if (col >= 0 && col <= NX - 3) {
                        azlo[c] = __ldcs(az0r + col);
                        azk[c]  = __ldcs(az1r + col);
                    }
                }
                #pragma unroll
                for (int c = 0; c < 4; c++) {
                    const int xi = x + c;
                    if (xi >= 1 && xi <= NX - 2) {
                        axx[c] = (axk[c + 1] - axk[c]) * INV_H_F;
                        azz[c] = (azk[c] - azlo[c]) * INV_H_F;
                    }
                }
            }
        }

        const float px_in[4] = {pxv.x, pxv.y, pxv.z, pxv.w};
        const float pz_in[4] = {pzv.x, pzv.y, pzv.z, pzv.w};
        const float sr_in[4] = {srv.x, srv.y, srv.z, srv.w};
        const float m_in[4]  = {mv.x, mv.y, mv.z, mv.w};
        const float sx_in[4] = {sxv.x, sxv.y, sxv.z, sxv.w};
        const float sz_in[4] = {szv.x, szv.y, szv.z, szv.w};

        float pxn[4], pzn[4], pv[4];
        #pragma unroll
        for (int c = 0; c < 4; c++) {
            const float sx = sx_in[c] * HDT_F;
            const float sz = sz_in[c] * HDT_F;
            pxn[c] = __fdividef(fmaf(m_in[c], axx[c], (1.f - sx) * px_in[c]), 1.f + sx);
            pzn[c] = __fdividef(fmaf(m_in[c], azz[c], (1.f - sz) * pz_in[c]), 1.f + sz);
            pv[c]  = pxn[c] + pzn[c] + sr_in[c] * DT_F;
        }

        __stcs((float4*)(oPx + g3), make_float4(pxn[0], pxn[1], pxn[2], pxn[3]));
        __stcs((float4*)(oPz + g3), make_float4(pzn[0], pzn[1], pzn[2], pzn[3]));
        __stcs((float4*)(oP  + g3), make_float4(pv[0], pv[1], pv[2], pv[3]));
        *(float4*)&sP[ty][4 * tx] = make_float4(pv[0], pv[1], pv[2], pv[3]);
    }

    // z==0 fixup: phase 2b needs Az row 0, which phase 1 didn't load (zin false)
    if (z == 0 && x < NX) {
        const float* az1r = Az + sOffAz;   // row 0
        #pragma unroll
        for (int c = 0; c < 4; c++) {
            const int col = x - 1 + c;
            if (col >= 0 && col <= NX - 3) azk[c] = __ldcs(az1r + col);
        }
    }

    // ---- Halo: bottom row (dz=TZ, cols 0..127) and right column (dx=TX, rows 0..7) ----
    if (tid < TX) {                         // 128 threads: halo row
        const int hz = z0 + TZ;
        const int hx = x0 + tid;
        if (hz < NZ && hx < NX)
            sP[TZ][tid] = compute_p_point(Px, Pz, Ax, Az, src, m2dt, sigx, sigz,
                                          sOffP, sOffAx, sOffAz, hz, hx);
    } else if (tid < TX + TZ) {             // 8 threads: halo column
        const int hz = z0 + (tid - TX);
        const int hx = x0 + TX;
        if (hx < NX)
            sP[tid - TX][TX] = compute_p_point(Px, Pz, Ax, Az, src, m2dt, sigx, sigz,
                                               sOffP, sOffAx, sOffAz, hz, hx);
    }

    __syncthreads();

    // ---- Phase 2a: Ax_n at row i = z0+ty-1, cols jb..jb+3 ----
    {
        const int i  = z0 + ty - 1;
        const int jb = x0 + 4 * tx;
        if (i >= 0 && i <= NZ - 3) {
            const float4 pvv = *(const float4*)&sP[ty][4 * tx];
            const float  pe  = sP[ty][4 * tx + 4];
            const float d[4] = {(pvv.y - pvv.x) * INV_H_F,
                                (pvv.z - pvv.y) * INV_H_F,
                                (pvv.w - pvv.z) * INV_H_F,
                                (pe    - pvv.w) * INV_H_F};
            const int base = sOffAx + i * (NX - 1) + jb;
            const float* sxr = sxh + i * (NX - 1) + jb;
            #pragma unroll
            for (int c = 0; c < 4; c++) {
                if (jb + c <= NX - 2) {
                    const float sv = sxr[c] * HDT_F;
                    __stcs(oAx + base + c,
                           __fdividef(fmaf(DT_F, d[c], (1.f - sv) * axk[c + 1]), 1.f + sv));
                }
            }
        }
    }

    // ---- Phase 2b: Az_n at row i = z0+ty, cols jb..jb+3 (jb = x0+4tx-1) ----
    {
        const int i  = z0 + ty;
        const int jb = x0 + 4 * tx - 1;
        if (i <= NZ - 2) {
            const float4 pt = *(const float4*)&sP[ty][4 * tx];
            const float4 pb = *(const float4*)&sP[ty + 1][4 * tx];
            const float d[4] = {(pb.x - pt.x) * INV_H_F,
                                (pb.y - pt.y) * INV_H_F,
                                (pb.z - pt.z) * INV_H_F,
                                (pb.w - pt.w) * INV_H_F};
            const int base = sOffAz + i * (NX - 2) + jb;
            const float* szr = szh + i * (NX - 2) + jb;
            #pragma unroll
            for (int c = 0; c < 4; c++) {
                const int j = jb + c;
                if (j >= 0 && j <= NX - 3) {
                    const float sv = szr[c] * HDT_F;
                    __stcs(oAz + base + c,
                           __fdividef(fmaf(DT_F, d[c], (1.f - sv) * azk[c]), 1.f + sv));
                }
            }
        }
    }
}

extern "C" void kernel_launch(void* const* d_in, const int* in_sizes, int n_in,
                              void* d_out, int out_size)
{
    const float* Px   = (const float*)d_in[0];
    const float* Pz   = (const float*)d_in[1];
    const float* Ax   = (const float*)d_in[2];
    const float* Az   = (const float*)d_in[3];
    const float* src  = (const float*)d_in[4];
    const float* m2dt = (const float*)d_in[5];
    const float* sigx = (const float*)d_in[6];
    const float* sxh  = (const float*)d_in[7];
    const float* sigz = (const float*)d_in[8];
    const float* szh  = (const float*)d_in[9];

    float* out = (float*)d_out;
    const long long NP  = (long long)NS * NZ * NX;
    const long long NAX = (long long)NS * (NZ - 2) * (NX - 1);
    const long long NAZ = (long long)NS * (NZ - 1) * (NX - 2);

    float* oPx = out;
    float* oPz = oPx + NP;
    float* oAx = oPz + NP;
    float* oAz = oAx + NAX;
    float* oP  = oAz + NAZ;

    dim3 block(32, TZ, 1);
    dim3 grid((NX + TX - 1) / TX, (NZ + TZ - 1) / TZ, NS);

    pml_step_kernel<<<grid, block>>>(Px, Pz, Ax, Az, src,
                                     m2dt, sigx, sxh, sigz, szh,
                                     oPx, oPz, oAx, oAz, oP);
}